// round 5
// baseline (speedup 1.0000x reference)
#include <cuda_runtime.h>
#include <cstdint>

#define AREAS   10
#define NPA     192
#define CDIM    128
#define NDIM    1920
#define MROWS   32768
#define OUTC    1280
#define CHUNK_M 8192
#define NCHUNK  (MROWS / CHUNK_M)
#define KT      12
#define PR      8
#define MB_N    (CHUNK_M / 128)       // 64 M-tiles per chunk
#define TPB     2                     // M-tiles per gemm block

#define SROW_P  1924

// xg layout: [(mb*AREAS+a)*KT + kt][r(128)][kr(4)][i(4)]
__device__ float g_xg[(size_t)MB_N * AREAS * KT * 128 * 16];
// Wt layout: [a][kt][n(128)][kr(4)][i(4)]
__device__ float g_Wt[AREAS * KT * 128 * 16];
__device__ int   g_src[NDIM];
__device__ int   g_gperm[NDIM];

__device__ __forceinline__ float cvt_tf32(float v) {
    uint32_t u;
    asm("cvt.rna.tf32.f32 %0, %1;" : "=r"(u) : "f"(v));
    return __uint_as_float(u);
}

#define CP_ASYNC16(dst, src) \
    asm volatile("cp.async.cg.shared.global [%0], [%1], 16;" :: "r"(dst), "l"(src))
#define CP_COMMIT() asm volatile("cp.async.commit_group;" ::: "memory")
#define CP_WAIT0()  asm volatile("cp.async.wait_group 0;" ::: "memory")

// ---------------------------------------------------------------------------
__global__ void setup_src_kernel(const int* __restrict__ nr) {
    const int warp = threadIdx.x >> 5, lane = threadIdx.x & 31;
    if (warp < AREAS) {
        int cnt = 0;
        for (int base = 0; base < NDIM; base += 32) {
            const int n = base + lane;
            const bool m = (nr[n] == warp);
            const unsigned bal = __ballot_sync(0xffffffffu, m);
            if (m) g_src[warp * NPA + cnt + __popc(bal & ((1u << lane) - 1u))] = n;
            cnt += __popc(bal);
        }
    }
}

__global__ void gperm_kernel() {
    int q = blockIdx.x * 256 + threadIdx.x;
    if (q < NDIM) {
        int i   = q & 3;
        int kr  = (q >> 2) & 3;
        int akt = q >> 4;
        int a = akt / KT, kt = akt % KT;
        g_gperm[q] = g_src[a * NPA + kt * 16 + kr + 4 * i];
    }
}

__global__ void wcvt_kernel(const float* __restrict__ W) {
    int o = blockIdx.x * 256 + threadIdx.x;
    if (o < AREAS * KT * 128 * 16) {
        int i  = o & 3;
        int kr = (o >> 2) & 3;
        int n  = (o >> 4) & 127;
        int kt = (o >> 11) % KT;
        int a  = o / (KT * 128 * 16);
        int k  = kt * 16 + kr + 4 * i;
        g_Wt[o] = cvt_tf32(W[(a * NPA + k) * CDIM + n]);
    }
}

// ---------------------------------------------------------------------------
// Permute (R4 version: coalesced per-warp slab stores).
// ---------------------------------------------------------------------------
__global__ __launch_bounds__(256, 3)
void permute_kernel(const float* __restrict__ x, int chunk_row0) {
    __shared__ float srow[PR * SROW_P];
    const int tid  = threadIdx.x;
    const int warp = tid >> 5, lane = tid & 31;
    const int r0   = blockIdx.x * PR;
    const int mb   = r0 >> 7;
    const int rloc = r0 & 127;

    const float4* x4 = (const float4*)(x + ((size_t)chunk_row0 + r0) * NDIM);
    #pragma unroll
    for (int s = 0; s < (PR * NDIM / 4) / 256; s++) {
        int i = tid + s * 256;
        int row = i / 480, c4 = i % 480;
        *(float4*)(srow + row * SROW_P + c4 * 4) = x4[i];
    }
    __syncthreads();

    const int row = lane >> 2;
    const int kr  = lane & 3;
    const float* sr = srow + row * SROW_P;
    const size_t slab0 = (size_t)mb * (AREAS * KT);
    const int dst_off = (rloc + row) * 16 + kr * 4;

    #pragma unroll
    for (int it = 0; it < (AREAS * KT) / 8; it++) {
        const int akt = warp * 15 + it;
        const int4 g = *(const int4*)(g_gperm + (akt * 4 + kr) * 4);
        float4 v;
        v.x = cvt_tf32(sr[g.x]);
        v.y = cvt_tf32(sr[g.y]);
        v.z = cvt_tf32(sr[g.z]);
        v.w = cvt_tf32(sr[g.w]);
        *(float4*)(g_xg + (slab0 + akt) * 2048 + dst_off) = v;
    }
}

// ---------------------------------------------------------------------------
// GEMM: block = (mb-pair, area). 2 CTAs/SM. B slab loaded once, reused for
// TPB=2 M-tiles. A streamed from L2 with register prefetch across tiles.
// ---------------------------------------------------------------------------
#define B_SLAB_F (KT * 128 * 16)
#define SMEM_BYTES (B_SLAB_F * 4)     // 98304

__global__ __launch_bounds__(256, 2)
void gemm_kernel(const float* __restrict__ bias, float* __restrict__ out,
                 int chunk_row0) {
    extern __shared__ float Bs[];
    const int a    = blockIdx.y;
    const int mb0  = blockIdx.x * TPB;
    const int tid  = threadIdx.x;
    const int warp = tid >> 5, lane = tid & 31;
    const int wm = warp >> 1;
    const int wn = warp & 1;
    const int qr = lane >> 2;
    const int kr = lane & 3;

    const float* Wsl = g_Wt + (size_t)a * B_SLAB_F;
    #pragma unroll
    for (int s = 0; s < (B_SLAB_F / 4) / 256; s++) {
        int i = tid + s * 256;
        uint32_t dst = (uint32_t)__cvta_generic_to_shared(Bs + i * 4);
        CP_ASYNC16(dst, Wsl + (size_t)i * 4);
    }
    CP_COMMIT();

    float2 bv[8];
    #pragma unroll
    for (int nt = 0; nt < 8; nt++)
        bv[nt] = *(const float2*)(bias + a * CDIM + wn * 64 + nt * 8 + kr * 2);

    const int roff[2] = { wm * 32 + qr, wm * 32 + 8 + qr };

    // prefetch A for first tile, kt=0 (overlaps the slab cp.async)
    const float* Ag = g_xg + ((size_t)mb0 * AREAS + a) * KT * 2048;
    float4 areg[2][2];
    #pragma unroll
    for (int mt = 0; mt < 2; mt++)
        #pragma unroll
        for (int h = 0; h < 2; h++)
            areg[mt][h] = *(const float4*)(Ag + (roff[h] + mt * 16) * 16 + kr * 4);

    CP_WAIT0();
    __syncthreads();

    #pragma unroll
    for (int t = 0; t < TPB; t++) {
        const int mb = mb0 + t;
        const float* Acur = g_xg + ((size_t)mb * AREAS + a) * KT * 2048;

        float acc[2][8][4];
        #pragma unroll
        for (int i = 0; i < 2; i++)
            #pragma unroll
            for (int j = 0; j < 8; j++)
                #pragma unroll
                for (int k = 0; k < 4; k++) acc[i][j][k] = 0.f;

        #pragma unroll
        for (int kt = 0; kt < KT; kt++) {
            float4 curA[2][2];
            #pragma unroll
            for (int mt = 0; mt < 2; mt++)
                #pragma unroll
                for (int h = 0; h < 2; h++) curA[mt][h] = areg[mt][h];

            const float* An;
            if (kt + 1 < KT)      An = Acur + (kt + 1) * 2048;
            else if (t + 1 < TPB) An = g_xg + ((size_t)(mb + 1) * AREAS + a) * KT * 2048;
            else                  An = Acur;
            #pragma unroll
            for (int mt = 0; mt < 2; mt++)
                #pragma unroll
                for (int h = 0; h < 2; h++)
                    areg[mt][h] = *(const float4*)(An + (roff[h] + mt * 16) * 16 + kr * 4);

            float4 bfr[8];
            #pragma unroll
            for (int nt = 0; nt < 8; nt++) {
                int n = wn * 64 + nt * 8 + qr;
                bfr[nt] = *(const float4*)(Bs + (kt * 128 + n) * 16 + kr * 4);
            }

            #pragma unroll
            for (int k8 = 0; k8 < 2; k8++) {
                #pragma unroll
                for (int mt = 0; mt < 2; mt++) {
                    uint32_t a0, a1, a2, a3;
                    if (k8 == 0) {
                        a0 = __float_as_uint(curA[mt][0].x);
                        a1 = __float_as_uint(curA[mt][1].x);
                        a2 = __float_as_uint(curA[mt][0].y);
                        a3 = __float_as_uint(curA[mt][1].y);
                    } else {
                        a0 = __float_as_uint(curA[mt][0].z);
                        a1 = __float_as_uint(curA[mt][1].z);
                        a2 = __float_as_uint(curA[mt][0].w);
                        a3 = __float_as_uint(curA[mt][1].w);
                    }
                    #pragma unroll
                    for (int nt = 0; nt < 8; nt++) {
                        uint32_t b0 = __float_as_uint(k8 == 0 ? bfr[nt].x : bfr[nt].z);
                        uint32_t b1 = __float_as_uint(k8 == 0 ? bfr[nt].y : bfr[nt].w);
                        asm volatile(
                            "mma.sync.aligned.m16n8k8.row.col.f32.tf32.tf32.f32 "
                            "{%0,%1,%2,%3},{%4,%5,%6,%7},{%8,%9},{%0,%1,%2,%3};"
                            : "+f"(acc[mt][nt][0]), "+f"(acc[mt][nt][1]),
                              "+f"(acc[mt][nt][2]), "+f"(acc[mt][nt][3])
                            : "r"(a0), "r"(a1), "r"(a2), "r"(a3), "r"(b0), "r"(b1));
                    }
                }
            }
        }

        #pragma unroll
        for (int mt = 0; mt < 2; mt++) {
            const int r0g = chunk_row0 + mb * 128 + wm * 32 + mt * 16 + qr;
            #pragma unroll
            for (int nt = 0; nt < 8; nt++) {
                const int c = wn * 64 + nt * 8 + kr * 2;
                float2 v0 = make_float2(acc[mt][nt][0] + bv[nt].x, acc[mt][nt][1] + bv[nt].y);
                float2 v1 = make_float2(acc[mt][nt][2] + bv[nt].x, acc[mt][nt][3] + bv[nt].y);
                *(float2*)(out + (size_t)r0g * OUTC + a * CDIM + c) = v0;
                *(float2*)(out + (size_t)(r0g + 8) * OUTC + a * CDIM + c) = v1;
            }
        }
    }
}

// ---------------------------------------------------------------------------
extern "C" void kernel_launch(void* const* d_in, const int* in_sizes, int n_in,
                              void* d_out, int out_size) {
    const float* x    = (const float*)d_in[0];
    const float* W    = (const float*)d_in[1];
    const float* bias = (const float*)d_in[2];
    const int*   nr   = (const int*)  d_in[3];
    float* out = (float*)d_out;

    static bool attr_set = false;
    if (!attr_set) {
        cudaFuncSetAttribute(gemm_kernel,
                             cudaFuncAttributeMaxDynamicSharedMemorySize, SMEM_BYTES);
        attr_set = true;
    }

    setup_src_kernel<<<1, 320>>>(nr);
    gperm_kernel<<<(NDIM + 255) / 256, 256>>>();
    wcvt_kernel<<<(AREAS * KT * 128 * 16 + 255) / 256, 256>>>(W);

    for (int ch = 0; ch < NCHUNK; ch++) {
        const int row0 = ch * CHUNK_M;
        permute_kernel<<<CHUNK_M / PR, 256>>>(x, row0);
        gemm_kernel<<<dim3(MB_N / TPB, AREAS), 256, SMEM_BYTES>>>(bias, out, row0);
    }
}

// round 8
// speedup vs baseline: 2.1091x; 2.1091x over previous
#include <cuda_runtime.h>
#include <cstdint>

#define AREAS   10
#define NPA     192
#define CDIM    128
#define NDIM    1920
#define MROWS   32768
#define OUTC    1280
#define CHUNK_M 4096
#define NCHUNK  (MROWS / CHUNK_M)     // 8
#define KT      12
#define PR      8
#define MB_N    (CHUNK_M / 128)       // 32 M-tiles per chunk
#define NBUF    2

#define SROW_P  1924

// xg: [buf][(mb*AREAS+a)*KT + kt][r(128)][kr(4)][i(4)]
#define XG_BUF_F ((size_t)MB_N * AREAS * KT * 2048)
__device__ float g_xg[NBUF * XG_BUF_F];
// Wt: [a][kt][n(128)][kr(4)][i(4)]
__device__ float g_Wt[AREAS * KT * 128 * 16];
__device__ int   g_src[NDIM];
__device__ int   g_gperm[NDIM];

__device__ __forceinline__ float cvt_tf32(float v) {
    uint32_t u;
    asm("cvt.rna.tf32.f32 %0, %1;" : "=r"(u) : "f"(v));
    return __uint_as_float(u);
}

#define CP_ASYNC16(dst, src) \
    asm volatile("cp.async.cg.shared.global [%0], [%1], 16;" :: "r"(dst), "l"(src))
#define CP_COMMIT() asm volatile("cp.async.commit_group;" ::: "memory")
#define CP_WAIT0()  asm volatile("cp.async.wait_group 0;" ::: "memory")

// ---------------------------------------------------------------------------
__global__ void setup_src_kernel(const int* __restrict__ nr) {
    const int warp = threadIdx.x >> 5, lane = threadIdx.x & 31;
    if (warp < AREAS) {
        int cnt = 0;
        for (int base = 0; base < NDIM; base += 32) {
            const int n = base + lane;
            const bool m = (nr[n] == warp);
            const unsigned bal = __ballot_sync(0xffffffffu, m);
            if (m) g_src[warp * NPA + cnt + __popc(bal & ((1u << lane) - 1u))] = n;
            cnt += __popc(bal);
        }
    }
}

__global__ void gperm_kernel() {
    int q = blockIdx.x * 256 + threadIdx.x;   // q = ((a*KT+kt)*4+kr)*4+i
    if (q < NDIM) {
        int i   = q & 3;
        int kr  = (q >> 2) & 3;
        int akt = q >> 4;
        int a = akt / KT, kt = akt % KT;
        g_gperm[q] = g_src[a * NPA + kt * 16 + kr + 4 * i];
    }
}

__global__ void wcvt_kernel(const float* __restrict__ W) {
    int o = blockIdx.x * 256 + threadIdx.x;
    if (o < AREAS * KT * 128 * 16) {
        int i  = o & 3;
        int kr = (o >> 2) & 3;
        int n  = (o >> 4) & 127;
        int kt = (o >> 11) % KT;
        int a  = o / (KT * 128 * 16);
        int k  = kt * 16 + kr + 4 * i;
        g_Wt[o] = cvt_tf32(W[(a * NPA + k) * CDIM + n]);
    }
}

// ---------------------------------------------------------------------------
// Permute 8 rows into fragment-order xg (R4 layout: per-warp coalesced stores).
// ---------------------------------------------------------------------------
__global__ __launch_bounds__(256, 3)
void permute_kernel(const float* __restrict__ x, int chunk_row0, int buf) {
    __shared__ float srow[PR * SROW_P];
    const int tid  = threadIdx.x;
    const int warp = tid >> 5, lane = tid & 31;
    const int r0   = blockIdx.x * PR;
    const int mb   = r0 >> 7;
    const int rloc = r0 & 127;

    const float4* x4 = (const float4*)(x + ((size_t)chunk_row0 + r0) * NDIM);
    #pragma unroll
    for (int s = 0; s < (PR * NDIM / 4) / 256; s++) {
        int i = tid + s * 256;
        int row = i / 480, c4 = i % 480;
        *(float4*)(srow + row * SROW_P + c4 * 4) = x4[i];
    }
    __syncthreads();

    const int row = lane >> 2;
    const int kr  = lane & 3;
    const float* sr = srow + row * SROW_P;
    float* xgb = g_xg + (size_t)buf * XG_BUF_F;
    const size_t slab0 = (size_t)mb * (AREAS * KT);
    const int dst_off = (rloc + row) * 16 + kr * 4;

    #pragma unroll
    for (int it = 0; it < (AREAS * KT) / 8; it++) {      // 15 iters
        const int akt = warp * 15 + it;
        const int4 g = *(const int4*)(g_gperm + (akt * 4 + kr) * 4);
        float4 v;
        v.x = cvt_tf32(sr[g.x]);
        v.y = cvt_tf32(sr[g.y]);
        v.z = cvt_tf32(sr[g.z]);
        v.w = cvt_tf32(sr[g.w]);
        *(float4*)(xgb + (slab0 + akt) * 2048 + dst_off) = v;
    }
}

// ---------------------------------------------------------------------------
// GEMM (R3 config): block=(mb, a), 2 CTAs/SM, B slab in SMEM, A from L2
// with register prefetch; legacy tf32 mma.sync.
// ---------------------------------------------------------------------------
#define B_SLAB_F (KT * 128 * 16)
#define SMEM_BYTES (B_SLAB_F * 4)     // 98304

__global__ __launch_bounds__(256, 2)
void gemm_kernel(const float* __restrict__ bias, float* __restrict__ out,
                 int chunk_row0, int buf) {
    extern __shared__ float Bs[];
    const int a    = blockIdx.y;
    const int mb   = blockIdx.x;
    const int tid  = threadIdx.x;
    const int warp = tid >> 5, lane = tid & 31;
    const int wm = warp >> 1;
    const int wn = warp & 1;
    const int qr = lane >> 2;
    const int kr = lane & 3;

    const float* Wsl = g_Wt + (size_t)a * B_SLAB_F;
    #pragma unroll
    for (int s = 0; s < (B_SLAB_F / 4) / 256; s++) {
        int i = tid + s * 256;
        uint32_t dst = (uint32_t)__cvta_generic_to_shared(Bs + i * 4);
        CP_ASYNC16(dst, Wsl + (size_t)i * 4);
    }
    CP_COMMIT();

    float2 bv[8];
    #pragma unroll
    for (int nt = 0; nt < 8; nt++)
        bv[nt] = *(const float2*)(bias + a * CDIM + wn * 64 + nt * 8 + kr * 2);

    const int roff[2] = { wm * 32 + qr, wm * 32 + 8 + qr };

    const float* Ag = g_xg + (size_t)buf * XG_BUF_F
                    + ((size_t)mb * AREAS + a) * KT * 2048;
    float4 areg[2][2];
    #pragma unroll
    for (int mt = 0; mt < 2; mt++)
        #pragma unroll
        for (int h = 0; h < 2; h++)
            areg[mt][h] = *(const float4*)(Ag + (roff[h] + mt * 16) * 16 + kr * 4);

    float acc[2][8][4];
    #pragma unroll
    for (int i = 0; i < 2; i++)
        #pragma unroll
        for (int j = 0; j < 8; j++)
            #pragma unroll
            for (int k = 0; k < 4; k++) acc[i][j][k] = 0.f;

    CP_WAIT0();
    __syncthreads();

    #pragma unroll
    for (int kt = 0; kt < KT; kt++) {
        float4 curA[2][2];
        #pragma unroll
        for (int mt = 0; mt < 2; mt++)
            #pragma unroll
            for (int h = 0; h < 2; h++) curA[mt][h] = areg[mt][h];

        if (kt + 1 < KT) {
            const float* An = Ag + (kt + 1) * 2048;
            #pragma unroll
            for (int mt = 0; mt < 2; mt++)
                #pragma unroll
                for (int h = 0; h < 2; h++)
                    areg[mt][h] = *(const float4*)(An + (roff[h] + mt * 16) * 16 + kr * 4);
        }

        float4 bfr[8];
        #pragma unroll
        for (int nt = 0; nt < 8; nt++) {
            int n = wn * 64 + nt * 8 + qr;
            bfr[nt] = *(const float4*)(Bs + (kt * 128 + n) * 16 + kr * 4);
        }

        #pragma unroll
        for (int k8 = 0; k8 < 2; k8++) {
            #pragma unroll
            for (int mt = 0; mt < 2; mt++) {
                uint32_t a0, a1, a2, a3;
                if (k8 == 0) {
                    a0 = __float_as_uint(curA[mt][0].x);
                    a1 = __float_as_uint(curA[mt][1].x);
                    a2 = __float_as_uint(curA[mt][0].y);
                    a3 = __float_as_uint(curA[mt][1].y);
                } else {
                    a0 = __float_as_uint(curA[mt][0].z);
                    a1 = __float_as_uint(curA[mt][1].z);
                    a2 = __float_as_uint(curA[mt][0].w);
                    a3 = __float_as_uint(curA[mt][1].w);
                }
                #pragma unroll
                for (int nt = 0; nt < 8; nt++) {
                    uint32_t b0 = __float_as_uint(k8 == 0 ? bfr[nt].x : bfr[nt].z);
                    uint32_t b1 = __float_as_uint(k8 == 0 ? bfr[nt].y : bfr[nt].w);
                    asm volatile(
                        "mma.sync.aligned.m16n8k8.row.col.f32.tf32.tf32.f32 "
                        "{%0,%1,%2,%3},{%4,%5,%6,%7},{%8,%9},{%0,%1,%2,%3};"
                        : "+f"(acc[mt][nt][0]), "+f"(acc[mt][nt][1]),
                          "+f"(acc[mt][nt][2]), "+f"(acc[mt][nt][3])
                        : "r"(a0), "r"(a1), "r"(a2), "r"(a3), "r"(b0), "r"(b1));
                }
            }
        }
    }

    #pragma unroll
    for (int mt = 0; mt < 2; mt++) {
        const int r0g = chunk_row0 + mb * 128 + wm * 32 + mt * 16 + qr;
        #pragma unroll
        for (int nt = 0; nt < 8; nt++) {
            const int c = wn * 64 + nt * 8 + kr * 2;
            float2 v0 = make_float2(acc[mt][nt][0] + bv[nt].x, acc[mt][nt][1] + bv[nt].y);
            float2 v1 = make_float2(acc[mt][nt][2] + bv[nt].x, acc[mt][nt][3] + bv[nt].y);
            *(float2*)(out + (size_t)r0g * OUTC + a * CDIM + c) = v0;
            *(float2*)(out + (size_t)(r0g + 8) * OUTC + a * CDIM + c) = v1;
        }
    }
}

// ---------------------------------------------------------------------------
extern "C" void kernel_launch(void* const* d_in, const int* in_sizes, int n_in,
                              void* d_out, int out_size) {
    const float* x    = (const float*)d_in[0];
    const float* W    = (const float*)d_in[1];
    const float* bias = (const float*)d_in[2];
    const int*   nr   = (const int*)  d_in[3];
    float* out = (float*)d_out;

    static bool inited = false;
    static cudaStream_t sP;
    static cudaEvent_t evFork, evP[NCHUNK], evG[NCHUNK];
    if (!inited) {
        cudaFuncSetAttribute(gemm_kernel,
                             cudaFuncAttributeMaxDynamicSharedMemorySize, SMEM_BYTES);
        cudaStreamCreateWithFlags(&sP, cudaStreamNonBlocking);
        cudaEventCreateWithFlags(&evFork, cudaEventDisableTiming);
        for (int i = 0; i < NCHUNK; i++) {
            cudaEventCreateWithFlags(&evP[i], cudaEventDisableTiming);
            cudaEventCreateWithFlags(&evG[i], cudaEventDisableTiming);
        }
        inited = true;
    }

    // setup on main stream
    setup_src_kernel<<<1, 320>>>(nr);
    gperm_kernel<<<(NDIM + 255) / 256, 256>>>();
    wcvt_kernel<<<(AREAS * KT * 128 * 16 + 255) / 256, 256>>>(W);

    // fork permute stream off main stream
    cudaEventRecord(evFork, 0);
    cudaStreamWaitEvent(sP, evFork, 0);

    for (int ch = 0; ch < NCHUNK; ch++) {
        const int row0 = ch * CHUNK_M;
        const int buf  = ch & 1;

        // permute(ch) on sP; must wait for gemm(ch-2) (previous user of buf)
        if (ch >= 2) cudaStreamWaitEvent(sP, evG[ch - 2], 0);
        permute_kernel<<<CHUNK_M / PR, 256, 0, sP>>>(x, row0, buf);
        cudaEventRecord(evP[ch], sP);

        // gemm(ch) on main stream; waits for its permute
        cudaStreamWaitEvent(0, evP[ch], 0);
        gemm_kernel<<<dim3(MB_N, AREAS), 256, SMEM_BYTES>>>(bias, out, row0, buf);
        cudaEventRecord(evG[ch], 0);
    }
    // main stream's last wait on evP[NCHUNK-1] already joined sP back.
}